// round 10
// baseline (speedup 1.0000x reference)
#include <cuda_runtime.h>
#include <cstdint>

// out[b] = sum_i cos(x[b,i]) * w[i] + bias ;  x: [1048576, 32] f32 (128B/row).
//
// LDG.256 version, R5's one-shot quantum: a "big group" = 8 rows = 1KB.
// Lane l holds the 32B chunk #l of the big group: row_in_bg = l>>2,
// chunk = l&3 (cols [8*chunk, 8*chunk+8)). Each warp processes exactly TWO
// big groups (16 rows = 2KB) with 2 independent 256-bit loads, dots 8 elements
// in registers, then a 2-step shfl_xor over the 4 lanes sharing a row.
// Grid = 8192 blocks x 256 thr (one-shot, scheduler keeps balancing).

__device__ __forceinline__ void ldg256(const float* p,
                                       float& a0, float& a1, float& a2, float& a3,
                                       float& a4, float& a5, float& a6, float& a7)
{
    asm volatile("ld.global.nc.v8.f32 {%0,%1,%2,%3,%4,%5,%6,%7}, [%8];"
                 : "=f"(a0), "=f"(a1), "=f"(a2), "=f"(a3),
                   "=f"(a4), "=f"(a5), "=f"(a6), "=f"(a7)
                 : "l"(p));
}

__device__ __forceinline__ float dot8(float a0, float a1, float a2, float a3,
                                      float a4, float a5, float a6, float a7,
                                      const float4& wlo, const float4& whi)
{
    return __cosf(a0) * wlo.x + __cosf(a1) * wlo.y
         + __cosf(a2) * wlo.z + __cosf(a3) * wlo.w
         + __cosf(a4) * whi.x + __cosf(a5) * whi.y
         + __cosf(a6) * whi.z + __cosf(a7) * whi.w;
}

__device__ __forceinline__ float reduce4(float s)
{
    s += __shfl_xor_sync(0xffffffffu, s, 1);
    s += __shfl_xor_sync(0xffffffffu, s, 2);
    return s;
}

__global__ void __launch_bounds__(256, 8) hybrid_regression_kernel(
    const float* __restrict__ x,
    const float* __restrict__ w,
    const float* __restrict__ bias,
    float*       __restrict__ out,
    int nrows)
{
    int gtid  = blockIdx.x * blockDim.x + threadIdx.x;
    int warp  = gtid >> 5;
    int lane  = gtid & 31;
    int chunk = lane & 3;          // 32B chunk within a 128B row
    int rsub  = lane >> 2;         // row within the 8-row big group

    int row0 = warp * 16;          // 2 big groups = 16 rows per warp, one shot
    if (row0 >= nrows) return;

    const float4* w4 = reinterpret_cast<const float4*>(w);
    float4 wlo = w4[chunk * 2 + 0];
    float4 whi = w4[chunk * 2 + 1];
    float  bb  = bias[0];

    const float* p = x + (size_t)row0 * 32 + lane * 8;   // lane's 32B chunk

    if (row0 + 16 <= nrows) {
        float a0,a1,a2,a3,a4,a5,a6,a7;
        float b0,b1,b2,b3,b4,b5,b6,b7;
        // two independent 256-bit coalesced loads (1KB each warp-wide)
        ldg256(p,       a0,a1,a2,a3,a4,a5,a6,a7);
        ldg256(p + 256, b0,b1,b2,b3,b4,b5,b6,b7);

        float s0 = reduce4(dot8(a0,a1,a2,a3,a4,a5,a6,a7, wlo, whi));
        float s1 = reduce4(dot8(b0,b1,b2,b3,b4,b5,b6,b7, wlo, whi));

        if (chunk == 0) {
            int r = row0 + rsub;
            out[r]     = s0 + bb;
            out[r + 8] = s1 + bb;
        }
    } else {
        // tail (not hit for B=1048576): scalar per-row fallback
        for (int r = row0 + lane; r < nrows; r += 32) {
            float s = 0.f;
            for (int i = 0; i < 32; ++i)
                s += __cosf(x[(size_t)r * 32 + i]) * w[i];
            out[r] = s + bb;
        }
    }
}

extern "C" void kernel_launch(void* const* d_in, const int* in_sizes, int n_in,
                              void* d_out, int out_size)
{
    const float* x    = (const float*)d_in[0];   // [B, 32]
    // d_in[1] = theta: mathematically dead (RZ phase leaves <Z> unchanged)
    const float* w    = (const float*)d_in[2];   // [1, 32]
    const float* b    = (const float*)d_in[3];   // [1]
    float* out        = (float*)d_out;

    int nrows = in_sizes[0] / 32;                // 1048576

    int threads = 256;                           // 8 warps
    int rows_per_block = 8 * 16;                 // 128 rows
    int blocks = (nrows + rows_per_block - 1) / rows_per_block;   // 8192

    hybrid_regression_kernel<<<blocks, threads>>>(x, w, b, out, nrows);
}

// round 11
// speedup vs baseline: 1.0139x; 1.0139x over previous
#include <cuda_runtime.h>

// out[b] = sum_i cos(x[b,i]) * w[i] + bias ;  x: [1048576, 32] f32.
//
// One-shot warps: each warp processes exactly ONE batch of 4 groups
// (4 rows/group * 4 groups = 16 rows = 2KB), with 4 independent front-batched
// LDG.128 (MLP=4), then reduces and exits. Grid = 8192 blocks (~7 waves) so
// the CTA scheduler continuously load-balances; the kernel tail is one 2KB
// batch instead of a long per-warp stream.
//
// Best-measured configuration across the 10-round sweep:
//   bench 25.06us, ncu 23.46us, DRAM 74.6%, HBM 5.90 TB/s.
// Falsified alternatives: single-wave persistent (71%), MLP=8 regs (72%),
// cp.async SMEM staging (68%), LDG.256 (65%), 128-thr blocks (73.9%).
//
// Lane l holds float4 #l of a 512B group; chunk = l&7 selects the weight quad;
// 3-step shfl_xor within each 8-lane subgroup yields the 4 row sums.

__device__ __forceinline__ float group_dot(const float4& xv, const float4& wv)
{
    return __cosf(xv.x) * wv.x + __cosf(xv.y) * wv.y
         + __cosf(xv.z) * wv.z + __cosf(xv.w) * wv.w;
}

__device__ __forceinline__ float reduce8(float s)
{
    s += __shfl_xor_sync(0xffffffffu, s, 1);
    s += __shfl_xor_sync(0xffffffffu, s, 2);
    s += __shfl_xor_sync(0xffffffffu, s, 4);
    return s;
}

__global__ void __launch_bounds__(256, 8) hybrid_regression_kernel(
    const float4* __restrict__ x4,
    const float*  __restrict__ w,
    const float*  __restrict__ bias,
    float*        __restrict__ out,
    int ngroups)
{
    int gtid  = blockIdx.x * blockDim.x + threadIdx.x;
    int warp  = gtid >> 5;
    int lane  = gtid & 31;
    int chunk = lane & 7;
    int sub   = lane >> 3;

    int g0 = warp * 4;                      // 4 groups per warp, one shot
    if (g0 >= ngroups) return;

    float4 wv = reinterpret_cast<const float4*>(w)[chunk];

    const float4* p = x4 + (size_t)g0 * 32 + lane;

    if (g0 + 4 <= ngroups) {
        // 4 independent coalesced 512B loads, front-batched (MLP=4)
        float4 xv0 = __ldcs(p +  0);
        float4 xv1 = __ldcs(p + 32);
        float4 xv2 = __ldcs(p + 64);
        float4 xv3 = __ldcs(p + 96);

        float bb = bias[0];

        float s0 = reduce8(group_dot(xv0, wv));
        float s1 = reduce8(group_dot(xv1, wv));
        float s2 = reduce8(group_dot(xv2, wv));
        float s3 = reduce8(group_dot(xv3, wv));

        if (chunk == 0) {
            int r = g0 * 4 + sub;
            out[r +  0] = s0 + bb;
            out[r +  4] = s1 + bb;
            out[r +  8] = s2 + bb;
            out[r + 12] = s3 + bb;
        }
    } else {
        // tail (not hit for B=1048576, kept for generality)
        float bb = bias[0];
        for (int g = g0; g < ngroups; ++g) {
            float4 xv = __ldcs(x4 + (size_t)g * 32 + lane);
            float s = reduce8(group_dot(xv, wv));
            if (chunk == 0) out[g * 4 + sub] = s + bb;
        }
    }
}

extern "C" void kernel_launch(void* const* d_in, const int* in_sizes, int n_in,
                              void* d_out, int out_size)
{
    const float* x    = (const float*)d_in[0];   // [B, 32]
    // d_in[1] = theta: mathematically dead (RZ phase leaves <Z> unchanged)
    const float* w    = (const float*)d_in[2];   // [1, 32]
    const float* b    = (const float*)d_in[3];   // [1]
    float* out        = (float*)d_out;

    int batch   = in_sizes[0] / 32;
    int ngroups = batch / 4;                      // 262144

    int threads = 256;
    int warps_per_block   = threads / 32;         // 8
    int groups_per_block  = warps_per_block * 4;  // 32
    int blocks = (ngroups + groups_per_block - 1) / groups_per_block;  // 8192

    hybrid_regression_kernel<<<blocks, threads>>>(
        (const float4*)x, w, b, out, ngroups);
}

// round 12
// speedup vs baseline: 1.0230x; 1.0089x over previous
#include <cuda_runtime.h>

// FINAL — best-measured configuration (reconfirmed twice: ncu 23.36/23.46us,
// DRAM 74.6-74.8%, HBM 5.90-5.92 TB/s, bench 25.06-25.31us).
//
// out[b] = sum_i cos(x[b,i]) * w[i] + bias ;  x: [1048576, 32] f32.
// theta input is mathematically dead (RZ phase leaves <Z> unchanged).
//
// One-shot warps: each warp processes exactly ONE batch of 4 groups
// (4 rows/group * 4 groups = 16 rows = 2KB), with 4 independent front-batched
// LDG.128 (MLP=4, __ldcs evict-first), then reduces and exits. Grid = 8192
// blocks (~7 waves) so the CTA scheduler continuously load-balances and the
// kernel tail is one 2KB batch.
//
// Falsified alternatives (DRAM%): single-wave persistent 71.1, MLP=8-in-regs
// 71.8, cp.async SMEM staging 67.7, LDG.256 65.3, 128-thr blocks 73.9,
// 16-group loops 73.1-73.6.
//
// Lane l holds float4 #l of a 512B group; chunk = l&7 selects the weight quad;
// 3-step shfl_xor within each 8-lane subgroup yields the 4 row sums.

__device__ __forceinline__ float group_dot(const float4& xv, const float4& wv)
{
    return __cosf(xv.x) * wv.x + __cosf(xv.y) * wv.y
         + __cosf(xv.z) * wv.z + __cosf(xv.w) * wv.w;
}

__device__ __forceinline__ float reduce8(float s)
{
    s += __shfl_xor_sync(0xffffffffu, s, 1);
    s += __shfl_xor_sync(0xffffffffu, s, 2);
    s += __shfl_xor_sync(0xffffffffu, s, 4);
    return s;
}

__global__ void __launch_bounds__(256, 8) hybrid_regression_kernel(
    const float4* __restrict__ x4,
    const float*  __restrict__ w,
    const float*  __restrict__ bias,
    float*        __restrict__ out,
    int ngroups)
{
    int gtid  = blockIdx.x * blockDim.x + threadIdx.x;
    int warp  = gtid >> 5;
    int lane  = gtid & 31;
    int chunk = lane & 7;
    int sub   = lane >> 3;

    int g0 = warp * 4;                      // 4 groups per warp, one shot
    if (g0 >= ngroups) return;

    float4 wv = reinterpret_cast<const float4*>(w)[chunk];

    const float4* p = x4 + (size_t)g0 * 32 + lane;

    if (g0 + 4 <= ngroups) {
        // 4 independent coalesced 512B loads, front-batched (MLP=4)
        float4 xv0 = __ldcs(p +  0);
        float4 xv1 = __ldcs(p + 32);
        float4 xv2 = __ldcs(p + 64);
        float4 xv3 = __ldcs(p + 96);

        float bb = bias[0];

        float s0 = reduce8(group_dot(xv0, wv));
        float s1 = reduce8(group_dot(xv1, wv));
        float s2 = reduce8(group_dot(xv2, wv));
        float s3 = reduce8(group_dot(xv3, wv));

        if (chunk == 0) {
            int r = g0 * 4 + sub;
            out[r +  0] = s0 + bb;
            out[r +  4] = s1 + bb;
            out[r +  8] = s2 + bb;
            out[r + 12] = s3 + bb;
        }
    } else {
        // tail (not hit for B=1048576, kept for generality)
        float bb = bias[0];
        for (int g = g0; g < ngroups; ++g) {
            float4 xv = __ldcs(x4 + (size_t)g * 32 + lane);
            float s = reduce8(group_dot(xv, wv));
            if (chunk == 0) out[g * 4 + sub] = s + bb;
        }
    }
}

extern "C" void kernel_launch(void* const* d_in, const int* in_sizes, int n_in,
                              void* d_out, int out_size)
{
    const float* x    = (const float*)d_in[0];   // [B, 32]
    // d_in[1] = theta: mathematically dead (RZ phase leaves <Z> unchanged)
    const float* w    = (const float*)d_in[2];   // [1, 32]
    const float* b    = (const float*)d_in[3];   // [1]
    float* out        = (float*)d_out;

    int batch   = in_sizes[0] / 32;
    int ngroups = batch / 4;                      // 262144

    int threads = 256;
    int warps_per_block   = threads / 32;         // 8
    int groups_per_block  = warps_per_block * 4;  // 32
    int blocks = (ngroups + groups_per_block - 1) / groups_per_block;  // 8192

    hybrid_regression_kernel<<<blocks, threads>>>(
        (const float4*)x, w, b, out, ngroups);
}